// round 2
// baseline (speedup 1.0000x reference)
#include <cuda_runtime.h>
#include <cuda_bf16.h>

#define BATCH_SIZE_D 8388608.0
#define REG1 0.01
#define REG2 0.001
#define LOG_CLAMP -100.0f

#define GRID_BLOCKS 1216   // 152 SMs * 8 CTA/SM
#define BLOCK_THREADS 256

// Per-block partials: x=bce, y=count, z=w1_ss, w=w2_ss. Written by owner block
// only -> no init needed. g_done statically zero; last block resets it to 0
// after finalize, so every graph replay starts from the same state.
__device__ float4 g_partials[GRID_BLOCKS];
__device__ unsigned int g_done = 0;

__device__ __forceinline__ float warp_reduce_f(float v) {
    #pragma unroll
    for (int off = 16; off > 0; off >>= 1)
        v += __shfl_xor_sync(0xFFFFFFFFu, v, off);
    return v;
}

__device__ __forceinline__ double warp_reduce_d(double v) {
    #pragma unroll
    for (int off = 16; off > 0; off >>= 1)
        v += __shfl_xor_sync(0xFFFFFFFFu, v, off);
    return v;
}

__global__ void __launch_bounds__(BLOCK_THREADS, 8) fused_loss_kernel(
    const float4* __restrict__ p4,
    const float4* __restrict__ l4,
    const float4* __restrict__ w14,
    const float4* __restrict__ w24,
    int nb4, int n14, int n24,
    float* __restrict__ out)
{
    float bce = 0.0f, cnt = 0.0f, s1 = 0.0f, s2 = 0.0f;

    const int tid    = blockIdx.x * BLOCK_THREADS + threadIdx.x;
    const int stride = GRID_BLOCKS * BLOCK_THREADS;

    // --- BCE + accuracy ---
    for (int i = tid; i < nb4; i += stride) {
        float4 pv = p4[i];
        float4 lv = l4[i];
        float pp[4] = {pv.x, pv.y, pv.z, pv.w};
        float ll[4] = {lv.x, lv.y, lv.z, lv.w};
        #pragma unroll
        for (int c = 0; c < 4; c++) {
            float lp = fmaxf(__logf(pp[c]),        LOG_CLAMP);  // log(p)
            float lq = fmaxf(__logf(1.0f - pp[c]), LOG_CLAMP);  // log(1-p)
            bce = fmaf(ll[c], lp, bce);
            bce = fmaf(1.0f - ll[c], lq, bce);
            cnt += (fabsf(pp[c] - ll[c]) < 0.5f) ? 1.0f : 0.0f;
        }
    }

    // --- ||w1||^2 ---
    for (int i = tid; i < n14; i += stride) {
        float4 v = w14[i];
        s1 = fmaf(v.x, v.x, s1);
        s1 = fmaf(v.y, v.y, s1);
        s1 = fmaf(v.z, v.z, s1);
        s1 = fmaf(v.w, v.w, s1);
    }

    // --- ||w2||^2 ---
    for (int i = tid; i < n24; i += stride) {
        float4 v = w24[i];
        s2 = fmaf(v.x, v.x, s2);
        s2 = fmaf(v.y, v.y, s2);
        s2 = fmaf(v.z, v.z, s2);
        s2 = fmaf(v.w, v.w, s2);
    }

    // --- block reduction ---
    __shared__ float smem[8][4];
    __shared__ bool is_last;
    const int lane = threadIdx.x & 31;
    const int warp = threadIdx.x >> 5;

    bce = warp_reduce_f(bce);
    cnt = warp_reduce_f(cnt);
    s1  = warp_reduce_f(s1);
    s2  = warp_reduce_f(s2);

    if (lane == 0) {
        smem[warp][0] = bce;
        smem[warp][1] = cnt;
        smem[warp][2] = s1;
        smem[warp][3] = s2;
    }
    __syncthreads();

    if (warp == 0) {
        float v0 = (lane < 8) ? smem[lane][0] : 0.0f;
        float v1 = (lane < 8) ? smem[lane][1] : 0.0f;
        float v2 = (lane < 8) ? smem[lane][2] : 0.0f;
        float v3 = (lane < 8) ? smem[lane][3] : 0.0f;
        v0 = warp_reduce_f(v0);
        v1 = warp_reduce_f(v1);
        v2 = warp_reduce_f(v2);
        v3 = warp_reduce_f(v3);
        if (lane == 0) {
            g_partials[blockIdx.x] = make_float4(v0, v1, v2, v3);
            __threadfence();
            unsigned int prev = atomicAdd(&g_done, 1u);
            is_last = (prev == GRID_BLOCKS - 1);
        }
    }
    __syncthreads();

    // --- last block: final reduce of all partials (fp64) + write output ---
    if (is_last) {
        double d0 = 0.0, d1 = 0.0, d2 = 0.0, d3 = 0.0;
        for (int i = threadIdx.x; i < GRID_BLOCKS; i += BLOCK_THREADS) {
            float4 v = g_partials[i];
            d0 += (double)v.x;
            d1 += (double)v.y;
            d2 += (double)v.z;
            d3 += (double)v.w;
        }
        d0 = warp_reduce_d(d0);
        d1 = warp_reduce_d(d1);
        d2 = warp_reduce_d(d2);
        d3 = warp_reduce_d(d3);

        __shared__ double dsm[8][4];
        if (lane == 0) {
            dsm[warp][0] = d0;
            dsm[warp][1] = d1;
            dsm[warp][2] = d2;
            dsm[warp][3] = d3;
        }
        __syncthreads();
        if (warp == 0) {
            double e0 = (lane < 8) ? dsm[lane][0] : 0.0;
            double e1 = (lane < 8) ? dsm[lane][1] : 0.0;
            double e2 = (lane < 8) ? dsm[lane][2] : 0.0;
            double e3 = (lane < 8) ? dsm[lane][3] : 0.0;
            e0 = warp_reduce_d(e0);
            e1 = warp_reduce_d(e1);
            e2 = warp_reduce_d(e2);
            e3 = warp_reduce_d(e3);
            if (lane == 0) {
                double B = BATCH_SIZE_D;
                double cross = -e0 / B;
                double reg = (REG1 * e2 + REG2 * e3) / (2.0 * B);
                out[0] = (float)(cross + reg);
                out[1] = (float)e1;
                __threadfence();
                g_done = 0;   // reset for next (deterministic) replay
            }
        }
    }
}

extern "C" void kernel_launch(void* const* d_in, const int* in_sizes, int n_in,
                              void* d_out, int out_size) {
    const float4* p4  = (const float4*)d_in[0];
    const float4* l4  = (const float4*)d_in[1];
    const float4* w14 = (const float4*)d_in[2];
    const float4* w24 = (const float4*)d_in[3];
    float* out = (float*)d_out;

    const int nb4 = in_sizes[0] / 4;
    const int n14 = in_sizes[2] / 4;
    const int n24 = in_sizes[3] / 4;

    fused_loss_kernel<<<GRID_BLOCKS, BLOCK_THREADS>>>(
        p4, l4, w14, w24, nb4, n14, n24, out);
}

// round 3
// speedup vs baseline: 1.0138x; 1.0138x over previous
#include <cuda_runtime.h>
#include <cuda_bf16.h>

#define BATCH_SIZE_D 8388608.0
#define REG1 0.01
#define REG2 0.001
#define LOG_CLAMP -100.0f

#define GRID_BLOCKS 608    // 152 SMs * 4 CTA/SM
#define BLOCK_THREADS 256
#define STRIDE (GRID_BLOCKS * BLOCK_THREADS)

__device__ float4 g_partials[GRID_BLOCKS];
__device__ unsigned int g_done = 0;

__device__ __forceinline__ float warp_reduce_f(float v) {
    #pragma unroll
    for (int off = 16; off > 0; off >>= 1)
        v += __shfl_xor_sync(0xFFFFFFFFu, v, off);
    return v;
}

__device__ __forceinline__ double warp_reduce_d(double v) {
    #pragma unroll
    for (int off = 16; off > 0; off >>= 1)
        v += __shfl_xor_sync(0xFFFFFFFFu, v, off);
    return v;
}

// BCE + accuracy for one float4 pair
__device__ __forceinline__ void bce_elem(float4 pv, float4 lv,
                                         float& bce, float& cnt) {
    float pp[4] = {pv.x, pv.y, pv.z, pv.w};
    float ll[4] = {lv.x, lv.y, lv.z, lv.w};
    #pragma unroll
    for (int c = 0; c < 4; c++) {
        float lp = fmaxf(__logf(pp[c]),        LOG_CLAMP);
        float lq = fmaxf(__logf(1.0f - pp[c]), LOG_CLAMP);
        bce = fmaf(ll[c], lp, bce);
        bce = fmaf(1.0f - ll[c], lq, bce);
        cnt += (fabsf(pp[c] - ll[c]) < 0.5f) ? 1.0f : 0.0f;
    }
}

__device__ __forceinline__ void ssq_elem(float4 v, float& s) {
    s = fmaf(v.x, v.x, s);
    s = fmaf(v.y, v.y, s);
    s = fmaf(v.z, v.z, s);
    s = fmaf(v.w, v.w, s);
}

__global__ void __launch_bounds__(BLOCK_THREADS, 4) fused_loss_kernel(
    const float4* __restrict__ p4,
    const float4* __restrict__ l4,
    const float4* __restrict__ w14,
    const float4* __restrict__ w24,
    int nb4, int n14, int n24,
    float* __restrict__ out)
{
    float bce = 0.0f, cnt = 0.0f, s1 = 0.0f, s2 = 0.0f;

    const int tid = blockIdx.x * BLOCK_THREADS + threadIdx.x;

    // ---- BCE + accuracy: unroll x4, 8 loads in flight ----
    int i = tid;
    for (; i + 3 * STRIDE < nb4; i += 4 * STRIDE) {
        float4 p0 = p4[i];
        float4 p1 = p4[i + STRIDE];
        float4 p2 = p4[i + 2 * STRIDE];
        float4 p3 = p4[i + 3 * STRIDE];
        float4 l0 = l4[i];
        float4 l1 = l4[i + STRIDE];
        float4 l2 = l4[i + 2 * STRIDE];
        float4 l3 = l4[i + 3 * STRIDE];
        bce_elem(p0, l0, bce, cnt);
        bce_elem(p1, l1, bce, cnt);
        bce_elem(p2, l2, bce, cnt);
        bce_elem(p3, l3, bce, cnt);
    }
    for (; i < nb4; i += STRIDE) {
        bce_elem(p4[i], l4[i], bce, cnt);
    }

    // ---- ||w1||^2: unroll x4 ----
    i = tid;
    for (; i + 3 * STRIDE < n14; i += 4 * STRIDE) {
        float4 v0 = w14[i];
        float4 v1 = w14[i + STRIDE];
        float4 v2 = w14[i + 2 * STRIDE];
        float4 v3 = w14[i + 3 * STRIDE];
        ssq_elem(v0, s1);
        ssq_elem(v1, s1);
        ssq_elem(v2, s1);
        ssq_elem(v3, s1);
    }
    for (; i < n14; i += STRIDE) {
        ssq_elem(w14[i], s1);
    }

    // ---- ||w2||^2: unroll x4 ----
    i = tid;
    for (; i + 3 * STRIDE < n24; i += 4 * STRIDE) {
        float4 v0 = w24[i];
        float4 v1 = w24[i + STRIDE];
        float4 v2 = w24[i + 2 * STRIDE];
        float4 v3 = w24[i + 3 * STRIDE];
        ssq_elem(v0, s2);
        ssq_elem(v1, s2);
        ssq_elem(v2, s2);
        ssq_elem(v3, s2);
    }
    for (; i < n24; i += STRIDE) {
        ssq_elem(w24[i], s2);
    }

    // ---- block reduction ----
    __shared__ float smem[8][4];
    __shared__ bool is_last;
    const int lane = threadIdx.x & 31;
    const int warp = threadIdx.x >> 5;

    bce = warp_reduce_f(bce);
    cnt = warp_reduce_f(cnt);
    s1  = warp_reduce_f(s1);
    s2  = warp_reduce_f(s2);

    if (lane == 0) {
        smem[warp][0] = bce;
        smem[warp][1] = cnt;
        smem[warp][2] = s1;
        smem[warp][3] = s2;
    }
    __syncthreads();

    if (warp == 0) {
        float v0 = (lane < 8) ? smem[lane][0] : 0.0f;
        float v1 = (lane < 8) ? smem[lane][1] : 0.0f;
        float v2 = (lane < 8) ? smem[lane][2] : 0.0f;
        float v3 = (lane < 8) ? smem[lane][3] : 0.0f;
        v0 = warp_reduce_f(v0);
        v1 = warp_reduce_f(v1);
        v2 = warp_reduce_f(v2);
        v3 = warp_reduce_f(v3);
        if (lane == 0) {
            g_partials[blockIdx.x] = make_float4(v0, v1, v2, v3);
            __threadfence();
            unsigned int prev = atomicAdd(&g_done, 1u);
            is_last = (prev == GRID_BLOCKS - 1);
        }
    }
    __syncthreads();

    // ---- last block: fp64 final reduce + output ----
    if (is_last) {
        double d0 = 0.0, d1 = 0.0, d2 = 0.0, d3 = 0.0;
        for (int j = threadIdx.x; j < GRID_BLOCKS; j += BLOCK_THREADS) {
            float4 v = g_partials[j];
            d0 += (double)v.x;
            d1 += (double)v.y;
            d2 += (double)v.z;
            d3 += (double)v.w;
        }
        d0 = warp_reduce_d(d0);
        d1 = warp_reduce_d(d1);
        d2 = warp_reduce_d(d2);
        d3 = warp_reduce_d(d3);

        __shared__ double dsm[8][4];
        if (lane == 0) {
            dsm[warp][0] = d0;
            dsm[warp][1] = d1;
            dsm[warp][2] = d2;
            dsm[warp][3] = d3;
        }
        __syncthreads();
        if (warp == 0) {
            double e0 = (lane < 8) ? dsm[lane][0] : 0.0;
            double e1 = (lane < 8) ? dsm[lane][1] : 0.0;
            double e2 = (lane < 8) ? dsm[lane][2] : 0.0;
            double e3 = (lane < 8) ? dsm[lane][3] : 0.0;
            e0 = warp_reduce_d(e0);
            e1 = warp_reduce_d(e1);
            e2 = warp_reduce_d(e2);
            e3 = warp_reduce_d(e3);
            if (lane == 0) {
                double B = BATCH_SIZE_D;
                double cross = -e0 / B;
                double reg = (REG1 * e2 + REG2 * e3) / (2.0 * B);
                out[0] = (float)(cross + reg);
                out[1] = (float)e1;
                __threadfence();
                g_done = 0;   // reset for deterministic graph replay
            }
        }
    }
}

extern "C" void kernel_launch(void* const* d_in, const int* in_sizes, int n_in,
                              void* d_out, int out_size) {
    const float4* p4  = (const float4*)d_in[0];
    const float4* l4  = (const float4*)d_in[1];
    const float4* w14 = (const float4*)d_in[2];
    const float4* w24 = (const float4*)d_in[3];
    float* out = (float*)d_out;

    const int nb4 = in_sizes[0] / 4;
    const int n14 = in_sizes[2] / 4;
    const int n24 = in_sizes[3] / 4;

    fused_loss_kernel<<<GRID_BLOCKS, BLOCK_THREADS>>>(
        p4, l4, w14, w24, nb4, n14, n24, out);
}

// round 4
// speedup vs baseline: 1.0534x; 1.0391x over previous
#include <cuda_runtime.h>
#include <cuda_bf16.h>

#define BATCH_SIZE_D 8388608.0
#define REG1 0.01
#define REG2 0.001
// clamp in log2 units: -100 / ln(2)
#define LG2_CLAMP -144.26950408889634f
#define LN2 0.6931471805599453

#define GRID_BLOCKS 608    // 152 SMs * 4 CTA/SM
#define BLOCK_THREADS 256
#define STRIDE (GRID_BLOCKS * BLOCK_THREADS)

__device__ float4 g_partials[GRID_BLOCKS];
__device__ unsigned int g_done = 0;

__device__ __forceinline__ float warp_reduce_f(float v) {
    #pragma unroll
    for (int off = 16; off > 0; off >>= 1)
        v += __shfl_xor_sync(0xFFFFFFFFu, v, off);
    return v;
}

__device__ __forceinline__ double warp_reduce_d(double v) {
    #pragma unroll
    for (int off = 16; off > 0; off >>= 1)
        v += __shfl_xor_sync(0xFFFFFFFFu, v, off);
    return v;
}

// BCE (in log2 units) + accuracy for one float4 pair
__device__ __forceinline__ void bce4(float4 pv, float4 lv,
                                     float& acc, float& cnt) {
    float pp[4] = {pv.x, pv.y, pv.z, pv.w};
    float ll[4] = {lv.x, lv.y, lv.z, lv.w};
    #pragma unroll
    for (int c = 0; c < 4; c++) {
        float lp = fmaxf(__log2f(pp[c]),        LG2_CLAMP);
        float lq = fmaxf(__log2f(1.0f - pp[c]), LG2_CLAMP);
        acc += lq;
        acc = fmaf(ll[c], lp - lq, acc);   // ll*lp + (1-ll)*lq
        cnt += (fabsf(pp[c] - ll[c]) < 0.5f) ? 1.0f : 0.0f;
    }
}

__device__ __forceinline__ void ssq4(float4 v, float& s) {
    s = fmaf(v.x, v.x, s);
    s = fmaf(v.y, v.y, s);
    s = fmaf(v.z, v.z, s);
    s = fmaf(v.w, v.w, s);
}

__global__ void __launch_bounds__(BLOCK_THREADS, 4) fused_loss_kernel(
    const float4* __restrict__ p4,
    const float4* __restrict__ l4,
    const float4* __restrict__ w14,
    const float4* __restrict__ w24,
    int nb4, int n14, int n24,
    float* __restrict__ out)
{
    float bce = 0.0f, cnt = 0.0f, s1 = 0.0f, s2 = 0.0f;

    const int tid = blockIdx.x * BLOCK_THREADS + threadIdx.x;

    // ---- Single fused loop: uniform memory demand across all 4 streams.
    // Per iteration: p[i], l[i], w1[i], w1[i+nb4], and w2[i] (first half).
    // In practice n14 == 2*nb4 and n24 == nb4/2; guards keep it general.
    for (int i = tid; i < nb4; i += STRIDE) {
        float4 pv = p4[i];
        float4 lv = l4[i];

        if (i < n14)       ssq4(w14[i], s1);
        int j = i + nb4;
        if (j < n14)       ssq4(w14[j], s1);
        if (i < n24)       ssq4(w24[i], s2);

        bce4(pv, lv, bce, cnt);
    }
    // cleanup for general shapes (empty with the actual sizes)
    for (int i = tid + 2 * nb4; i < n14; i += STRIDE) ssq4(w14[i], s1);
    for (int i = tid + nb4;     i < n24; i += STRIDE) ssq4(w24[i], s2);

    // ---- block reduction ----
    __shared__ float smem[8][4];
    __shared__ bool is_last;
    const int lane = threadIdx.x & 31;
    const int warp = threadIdx.x >> 5;

    bce = warp_reduce_f(bce);
    cnt = warp_reduce_f(cnt);
    s1  = warp_reduce_f(s1);
    s2  = warp_reduce_f(s2);

    if (lane == 0) {
        smem[warp][0] = bce;
        smem[warp][1] = cnt;
        smem[warp][2] = s1;
        smem[warp][3] = s2;
    }
    __syncthreads();

    if (warp == 0) {
        float v0 = (lane < 8) ? smem[lane][0] : 0.0f;
        float v1 = (lane < 8) ? smem[lane][1] : 0.0f;
        float v2 = (lane < 8) ? smem[lane][2] : 0.0f;
        float v3 = (lane < 8) ? smem[lane][3] : 0.0f;
        v0 = warp_reduce_f(v0);
        v1 = warp_reduce_f(v1);
        v2 = warp_reduce_f(v2);
        v3 = warp_reduce_f(v3);
        if (lane == 0) {
            g_partials[blockIdx.x] = make_float4(v0, v1, v2, v3);
            __threadfence();
            unsigned int prev = atomicAdd(&g_done, 1u);
            is_last = (prev == GRID_BLOCKS - 1);
        }
    }
    __syncthreads();

    // ---- last block: fp64 final reduce + output ----
    if (is_last) {
        double d0 = 0.0, d1 = 0.0, d2 = 0.0, d3 = 0.0;
        for (int k = threadIdx.x; k < GRID_BLOCKS; k += BLOCK_THREADS) {
            float4 v = g_partials[k];
            d0 += (double)v.x;
            d1 += (double)v.y;
            d2 += (double)v.z;
            d3 += (double)v.w;
        }
        d0 = warp_reduce_d(d0);
        d1 = warp_reduce_d(d1);
        d2 = warp_reduce_d(d2);
        d3 = warp_reduce_d(d3);

        __shared__ double dsm[8][4];
        if (lane == 0) {
            dsm[warp][0] = d0;
            dsm[warp][1] = d1;
            dsm[warp][2] = d2;
            dsm[warp][3] = d3;
        }
        __syncthreads();
        if (warp == 0) {
            double e0 = (lane < 8) ? dsm[lane][0] : 0.0;
            double e1 = (lane < 8) ? dsm[lane][1] : 0.0;
            double e2 = (lane < 8) ? dsm[lane][2] : 0.0;
            double e3 = (lane < 8) ? dsm[lane][3] : 0.0;
            e0 = warp_reduce_d(e0);
            e1 = warp_reduce_d(e1);
            e2 = warp_reduce_d(e2);
            e3 = warp_reduce_d(e3);
            if (lane == 0) {
                double B = BATCH_SIZE_D;
                double cross = -(LN2 * e0) / B;       // lg2 -> nats here
                double reg = (REG1 * e2 + REG2 * e3) / (2.0 * B);
                out[0] = (float)(cross + reg);
                out[1] = (float)e1;
                __threadfence();
                g_done = 0;   // reset for deterministic graph replay
            }
        }
    }
}

extern "C" void kernel_launch(void* const* d_in, const int* in_sizes, int n_in,
                              void* d_out, int out_size) {
    const float4* p4  = (const float4*)d_in[0];
    const float4* l4  = (const float4*)d_in[1];
    const float4* w14 = (const float4*)d_in[2];
    const float4* w24 = (const float4*)d_in[3];
    float* out = (float*)d_out;

    const int nb4 = in_sizes[0] / 4;
    const int n14 = in_sizes[2] / 4;
    const int n24 = in_sizes[3] / 4;

    fused_loss_kernel<<<GRID_BLOCKS, BLOCK_THREADS>>>(
        p4, l4, w14, w24, nb4, n14, n24, out);
}